// round 6
// baseline (speedup 1.0000x reference)
#include <cuda_runtime.h>
#include <cstdint>

// Problem constants (fixed by the reference implementation)
#define NFEAT  23
#define EMB    10
#define TOTALD 65      // sum(FEATURE_DIMS)
#define DMAXD  4
#define CH     230     // NFEAT * EMB
#define PAIRS  115     // CH / 2 — each thread owns an (e, e+1) pair of one feature
#define TR     32      // rows per smem tile
#define TILE_F4 ((TR * TOTALD) / 4)   // 520 float4 per tile
#define PIPE   3       // cp.async ring depth
#define NSM    152     // GB300
#define OCC    8
#define GRID   (NSM * OCC)   // 1216 persistent CTAs -> exactly one wave

__constant__ int c_dims[NFEAT] = {4,4,4,4,4,4,4,4,4,4,4,4,2,2,1,4,1,1,1,1,1,1,2};
__constant__ int c_offs[NFEAT] = {0,4,8,12,16,20,24,28,32,36,40,44,48,50,52,53,57,58,59,60,61,62,63};

__device__ __forceinline__ void cp_async16(void* smem_dst, const void* gsrc) {
    uint32_t s = (uint32_t)__cvta_generic_to_shared(smem_dst);
    asm volatile("cp.async.cg.shared.global [%0], [%1], 16;\n" :: "r"(s), "l"(gsrc));
}
#define CP_COMMIT() asm volatile("cp.async.commit_group;\n" ::: "memory")
#define CP_WAIT2()  asm volatile("cp.async.wait_group 2;\n" ::: "memory")

// blockDim=256: tid%128 = channel-pair index p (0..114 active), tid/128 = row
// phase. Persistent CTAs grid-stride over 32-row tiles with a 3-deep cp.async
// ring: while tile i is computed/stored, tiles i+1 and i+2 stream GMEM->SMEM.
// Exactly one commit_group per iteration => wait_group 2 guarantees tile i's
// data has landed. Buffer (i+2)%3 is rewritten only after the end-of-compute
// barrier of iteration i-1, which is the last reader of that buffer.
__global__ __launch_bounds__(256, OCC)
void Projection_5171140624940_kernel(const float* __restrict__ x,
                                     const float* __restrict__ W,
                                     const float* __restrict__ b,
                                     float* __restrict__ out,
                                     int rows)
{
    __shared__ __align__(16) float xs[PIPE][TR * TOTALD];   // 3 x 8320 B

    const int tid   = threadIdx.x;
    const int p     = tid & 127;
    const int rslot = tid >> 7;
    const bool active = (p < PAIRS);

    // Per-thread channel-pair metadata + register-resident weights.
    float w0[DMAXD], w1[DMAXD];
    float b0 = 0.f, b1 = 0.f;
    int off = 0, dim = 0;
    if (active) {
        const int f = p / 5;
        const int e = (p - f * 5) * 2;
        off = c_offs[f];
        dim = c_dims[f];
        #pragma unroll
        for (int j = 0; j < DMAXD; ++j) {
            w0[j] = __ldg(W + f * (DMAXD * EMB) + j * EMB + e);
            w1[j] = __ldg(W + f * (DMAXD * EMB) + j * EMB + e + 1);
        }
        b0 = __ldg(b + f * EMB + e);
        b1 = __ldg(b + f * EMB + e + 1);
    }

    const int ntiles = rows / TR;          // full tiles (rows % TR handled below)
    const int stride = gridDim.x;

    // Stage one full tile into smem buffer `buf` via cp.async (no reg round-trip).
    auto stage = [&](int bufIdx, int tile) {
        const float4* src = reinterpret_cast<const float4*>(
            x + (size_t)tile * TR * TOTALD);
        float4* dst = reinterpret_cast<float4*>(xs[bufIdx]);
        #pragma unroll
        for (int i = tid; i < TILE_F4; i += 256)
            cp_async16(dst + i, src + i);
    };

    // ---- Prologue: prefetch up to PIPE-1 tiles (one commit each, even if empty)
    #pragma unroll
    for (int k = 0; k < PIPE - 1; ++k) {
        const int t = blockIdx.x + k * stride;
        if (t < ntiles) stage(k, t);
        CP_COMMIT();
    }

    // ---- Main persistent loop ----
    int i = 0;
    for (int t = blockIdx.x; t < ntiles; t += stride, ++i) {
        const int tpre = t + (PIPE - 1) * stride;
        if (tpre < ntiles) stage((i + PIPE - 1) % PIPE, tpre);
        CP_COMMIT();
        CP_WAIT2();           // tile i's group (and all earlier) complete
        __syncthreads();

        if (active) {
            const float* xb = xs[i % PIPE];
            const size_t tileStart = (size_t)t * TR;
            #pragma unroll 4
            for (int lr = rslot; lr < TR; lr += 2) {
                const float* xr = xb + lr * TOTALD + off;
                float s0 = b0, s1 = b1;
                #pragma unroll
                for (int j = 0; j < DMAXD; ++j) {
                    if (j < dim) {
                        const float xv = xr[j];
                        s0 = fmaf(xv, w0[j], s0);
                        s1 = fmaf(xv, w1[j], s1);
                    }
                }
                // warp writes 256B contiguous; .cs streams past L2
                __stcs(reinterpret_cast<float2*>(
                           out + (tileStart + lr) * CH + 2 * p),
                       make_float2(s0, s1));
            }
        }
        __syncthreads();      // last read of xs[i%PIPE]; rewritten at iter i+1
    }

    // ---- Remainder rows (rows % TR != 0; dead for B=524288) ----
    const int remStart = ntiles * TR;
    if (remStart < rows && blockIdx.x == 0) {
        const int remRows = rows - remStart;
        for (int k = tid; k < remRows * TOTALD; k += 256)
            xs[0][k] = __ldcs(x + (size_t)remStart * TOTALD + k);
        __syncthreads();
        if (active) {
            for (int lr = rslot; lr < remRows; lr += 2) {
                const float* xr = xs[0] + lr * TOTALD + off;
                float s0 = b0, s1 = b1;
                #pragma unroll
                for (int j = 0; j < DMAXD; ++j) {
                    if (j < dim) {
                        const float xv = xr[j];
                        s0 = fmaf(xv, w0[j], s0);
                        s1 = fmaf(xv, w1[j], s1);
                    }
                }
                __stcs(reinterpret_cast<float2*>(
                           out + (size_t)(remStart + lr) * CH + 2 * p),
                       make_float2(s0, s1));
            }
        }
    }
}

extern "C" void kernel_launch(void* const* d_in, const int* in_sizes, int n_in,
                              void* d_out, int out_size)
{
    const float* x = (const float*)d_in[0];   // [B, 65] f32
    const float* W = (const float*)d_in[1];   // [23, 4, 10] f32 (masked)
    const float* b = (const float*)d_in[2];   // [23, 10] f32
    // d_in[3] = idx (int32) — compile-time constant metadata, ignored.
    float* out = (float*)d_out;               // [B, 23, 10] f32

    const int rows = in_sizes[0] / TOTALD;    // 524288
    int grid = GRID;
    const int ntiles = rows / TR;
    if (grid > ntiles && ntiles > 0) grid = ntiles;   // tiny-input safety

    Projection_5171140624940_kernel<<<grid, 256>>>(x, W, b, out, rows);
}

// round 7
// speedup vs baseline: 1.1014x; 1.1014x over previous
#include <cuda_runtime.h>
#include <cstdint>

// Problem constants (fixed by the reference implementation)
#define NFEAT  23
#define EMB    10
#define TOTALD 65      // sum(FEATURE_DIMS)
#define DMAXD  4
#define CH     230     // NFEAT * EMB
#define PAIRS  115     // CH / 2 — each thread owns an (e, e+1) pair of one feature
#define TR     32      // rows per smem tile
#define NTILES 4
#define RPB    (TR * NTILES)            // 128 rows per block
#define TILE_BYTES (TR * TOTALD * 4)    // 8320 B (multiple of 16)

__constant__ int c_dims[NFEAT] = {4,4,4,4,4,4,4,4,4,4,4,4,2,2,1,4,1,1,1,1,1,1,2};
__constant__ int c_offs[NFEAT] = {0,4,8,12,16,20,24,28,32,36,40,44,48,50,52,53,57,58,59,60,61,62,63};

// ---- mbarrier + bulk-copy helpers (single UBLKCP per tile: no LSU cost) ----
__device__ __forceinline__ uint32_t smem_u32(const void* p) {
    return (uint32_t)__cvta_generic_to_shared(p);
}
__device__ __forceinline__ void mbar_init(uint32_t mbar, uint32_t count) {
    asm volatile("mbarrier.init.shared.b64 [%0], %1;" :: "r"(mbar), "r"(count) : "memory");
}
__device__ __forceinline__ void mbar_expect_tx(uint32_t mbar, uint32_t bytes) {
    asm volatile("mbarrier.arrive.expect_tx.shared.b64 _, [%0], %1;"
                 :: "r"(mbar), "r"(bytes) : "memory");
}
__device__ __forceinline__ void bulk_g2s(uint32_t dst_s, const void* src,
                                         uint32_t bytes, uint32_t mbar) {
    asm volatile(
        "cp.async.bulk.shared::cta.global.mbarrier::complete_tx::bytes "
        "[%0], [%1], %2, [%3];"
        :: "r"(dst_s), "l"(src), "r"(bytes), "r"(mbar) : "memory");
}
__device__ __forceinline__ void mbar_wait(uint32_t mbar, uint32_t parity) {
    asm volatile(
        "{\n\t"
        ".reg .pred P;\n\t"
        "WAIT_%=:\n\t"
        "mbarrier.try_wait.parity.acquire.cta.shared::cta.b64 P, [%0], %1, 0x989680;\n\t"
        "@P bra.uni DONE_%=;\n\t"
        "bra.uni WAIT_%=;\n\t"
        "DONE_%=:\n\t"
        "}"
        :: "r"(mbar), "r"(parity) : "memory");
}

// blockDim=256: tid%128 = channel-pair index p (0..114 active), tid/128 = row
// phase. Per block: 4 contiguous 32-row tiles, double-buffered. Each tile is
// staged GMEM->SMEM by ONE cp.async.bulk (DMA engine, zero LSU occupancy)
// while the previous tile is computed and stored with coalesced 256B/warp
// float2 streaming stores.
__global__ __launch_bounds__(256, 8)
void Projection_5171140624940_kernel(const float* __restrict__ x,
                                     const float* __restrict__ W,
                                     const float* __restrict__ b,
                                     float* __restrict__ out,
                                     int rows)
{
    __shared__ __align__(16) float xs[2][TR * TOTALD];   // 2 x 8320 B
    __shared__ __align__(8)  uint64_t mb[2];

    const int tid   = threadIdx.x;
    const int p     = tid & 127;
    const int rslot = tid >> 7;
    const bool active = (p < PAIRS);

    // Per-thread channel-pair metadata + register-resident weights.
    float w0[DMAXD], w1[DMAXD];
    float b0 = 0.f, b1 = 0.f;
    int off = 0, dim = 0;
    if (active) {
        const int f = p / 5;
        const int e = (p - f * 5) * 2;
        off = c_offs[f];
        dim = c_dims[f];
        #pragma unroll
        for (int j = 0; j < DMAXD; ++j) {
            w0[j] = __ldg(W + f * (DMAXD * EMB) + j * EMB + e);
            w1[j] = __ldg(W + f * (DMAXD * EMB) + j * EMB + e + 1);
        }
        b0 = __ldg(b + f * EMB + e);
        b1 = __ldg(b + f * EMB + e + 1);
    }

    const int rBase = blockIdx.x * RPB;

    if (rBase + RPB <= rows) {
        // ---- Fast path: 4 full tiles, double-buffered bulk-copy pipeline ----
        const uint32_t mbs0 = smem_u32(&mb[0]);
        const uint32_t mbs1 = smem_u32(&mb[1]);
        const uint32_t xss0 = smem_u32(xs[0]);
        const uint32_t xss1 = smem_u32(xs[1]);

        if (tid == 0) {
            mbar_init(mbs0, 1);
            mbar_init(mbs1, 1);
            asm volatile("fence.proxy.async.shared::cta;" ::: "memory");
        }
        __syncthreads();

        if (tid == 0) {
            mbar_expect_tx(mbs0, TILE_BYTES);
            bulk_g2s(xss0, x + (size_t)rBase * TOTALD, TILE_BYTES, mbs0);
        }

        #pragma unroll
        for (int t = 0; t < NTILES; ++t) {
            const int buf = t & 1;
            // Prefetch tile t+1 into the other buffer. Its last reader was
            // iteration t-1, which ended with __syncthreads.
            if (tid == 0 && t + 1 < NTILES) {
                const uint32_t mbn  = buf ? mbs0 : mbs1;
                const uint32_t dstn = buf ? xss0 : xss1;
                mbar_expect_tx(mbn, TILE_BYTES);
                bulk_g2s(dstn, x + (size_t)(rBase + (t + 1) * TR) * TOTALD,
                         TILE_BYTES, mbn);
            }
            // Wait for tile t. Each barrier is reused every 2 tiles -> parity.
            mbar_wait(buf ? mbs1 : mbs0, (t >> 1) & 1);

            if (active) {
                const int tileStart = rBase + t * TR;
                const float* xb = xs[buf];
                #pragma unroll 4
                for (int lr = rslot; lr < TR; lr += 2) {
                    const float* xr = xb + lr * TOTALD + off;
                    float s0 = b0, s1 = b1;
                    #pragma unroll
                    for (int j = 0; j < DMAXD; ++j) {
                        if (j < dim) {
                            const float xv = xr[j];
                            s0 = fmaf(xv, w0[j], s0);
                            s1 = fmaf(xv, w1[j], s1);
                        }
                    }
                    // warp writes 256B contiguous; .cs streams past L2
                    __stcs(reinterpret_cast<float2*>(
                               out + (size_t)(tileStart + lr) * CH + 2 * p),
                           make_float2(s0, s1));
                }
            }
            __syncthreads();   // last read of xs[buf]; refilled at iter t+1
        }
    } else {
        // ---- Tail path (unused for B=524288): synchronous staging ----
        for (int t0 = 0; t0 < RPB; t0 += TR) {
            const int tileStart = rBase + t0;
            if (tileStart >= rows) break;
            const int tileRows = min(TR, rows - tileStart);

            const float* src = x + (size_t)tileStart * TOTALD;
            for (int i = tid; i < tileRows * TOTALD; i += 256)
                xs[0][i] = __ldcs(src + i);
            __syncthreads();

            if (active) {
                for (int lr = rslot; lr < tileRows; lr += 2) {
                    const float* xr = xs[0] + lr * TOTALD + off;
                    float s0 = b0, s1 = b1;
                    #pragma unroll
                    for (int j = 0; j < DMAXD; ++j) {
                        if (j < dim) {
                            const float xv = xr[j];
                            s0 = fmaf(xv, w0[j], s0);
                            s1 = fmaf(xv, w1[j], s1);
                        }
                    }
                    __stcs(reinterpret_cast<float2*>(
                               out + (size_t)(tileStart + lr) * CH + 2 * p),
                           make_float2(s0, s1));
                }
            }
            __syncthreads();
        }
    }
}

extern "C" void kernel_launch(void* const* d_in, const int* in_sizes, int n_in,
                              void* d_out, int out_size)
{
    const float* x = (const float*)d_in[0];   // [B, 65] f32
    const float* W = (const float*)d_in[1];   // [23, 4, 10] f32 (masked)
    const float* b = (const float*)d_in[2];   // [23, 10] f32
    // d_in[3] = idx (int32) — compile-time constant metadata, ignored.
    float* out = (float*)d_out;               // [B, 23, 10] f32

    const int rows = in_sizes[0] / TOTALD;    // 524288
    const int grid = (rows + RPB - 1) / RPB;  // 4096

    Projection_5171140624940_kernel<<<grid, 256>>>(x, W, b, out, rows);
}

// round 8
// speedup vs baseline: 1.1241x; 1.0206x over previous
#include <cuda_runtime.h>
#include <cstdint>

// Problem constants (fixed by the reference implementation)
#define NFEAT  23
#define EMB    10
#define TOTALD 65      // sum(FEATURE_DIMS)
#define DMAXD  4
#define CH     230     // NFEAT * EMB
#define PAIRS  115     // CH / 2 — each thread owns an (e, e+1) pair of one feature
#define TR     32      // rows per smem tile
#define NTILES 4
#define RPB    (TR * NTILES)            // 128 rows per block
#define PIPE   3                        // bulk-copy ring depth
#define TILE_BYTES (TR * TOTALD * 4)    // 8320 B (multiple of 16)

__constant__ int c_dims[NFEAT] = {4,4,4,4,4,4,4,4,4,4,4,4,2,2,1,4,1,1,1,1,1,1,2};
__constant__ int c_offs[NFEAT] = {0,4,8,12,16,20,24,28,32,36,40,44,48,50,52,53,57,58,59,60,61,62,63};

// ---- mbarrier + bulk-copy helpers (one UBLKCP per tile: zero LSU cost) ----
__device__ __forceinline__ uint32_t smem_u32(const void* p) {
    return (uint32_t)__cvta_generic_to_shared(p);
}
__device__ __forceinline__ void mbar_init(uint32_t mbar, uint32_t count) {
    asm volatile("mbarrier.init.shared.b64 [%0], %1;" :: "r"(mbar), "r"(count) : "memory");
}
__device__ __forceinline__ void mbar_expect_tx(uint32_t mbar, uint32_t bytes) {
    asm volatile("mbarrier.arrive.expect_tx.shared.b64 _, [%0], %1;"
                 :: "r"(mbar), "r"(bytes) : "memory");
}
__device__ __forceinline__ void bulk_g2s(uint32_t dst_s, const void* src,
                                         uint32_t bytes, uint32_t mbar) {
    asm volatile(
        "cp.async.bulk.shared::cta.global.mbarrier::complete_tx::bytes "
        "[%0], [%1], %2, [%3];"
        :: "r"(dst_s), "l"(src), "r"(bytes), "r"(mbar) : "memory");
}
__device__ __forceinline__ void mbar_wait(uint32_t mbar, uint32_t parity) {
    asm volatile(
        "{\n\t"
        ".reg .pred P;\n\t"
        "WAIT_%=:\n\t"
        "mbarrier.try_wait.parity.acquire.cta.shared::cta.b64 P, [%0], %1, 0x989680;\n\t"
        "@P bra.uni DONE_%=;\n\t"
        "bra.uni WAIT_%=;\n\t"
        "DONE_%=:\n\t"
        "}"
        :: "r"(mbar), "r"(parity) : "memory");
}

// blockDim=256: tid%128 = channel-pair index p (0..114 active), tid/128 = row
// phase. Per block: 4 contiguous 32-row tiles through a 3-deep bulk-DMA ring,
// so each tile's transfer is issued TWO compute phases before its wait (DRAM
// latency fully covered). Compute stores with coalesced 256B/warp float2
// streaming stores.
__global__ __launch_bounds__(256, 8)
void Projection_5171140624940_kernel(const float* __restrict__ x,
                                     const float* __restrict__ W,
                                     const float* __restrict__ b,
                                     float* __restrict__ out,
                                     int rows)
{
    __shared__ __align__(16) float xs[PIPE][TR * TOTALD];   // 3 x 8320 B
    __shared__ __align__(8)  uint64_t mb[PIPE];

    const int tid   = threadIdx.x;
    const int p     = tid & 127;
    const int rslot = tid >> 7;
    const bool active = (p < PAIRS);

    // Per-thread channel-pair metadata + register-resident weights.
    float w0[DMAXD], w1[DMAXD];
    float b0 = 0.f, b1 = 0.f;
    int off = 0, dim = 0;
    if (active) {
        const int f = p / 5;
        const int e = (p - f * 5) * 2;
        off = c_offs[f];
        dim = c_dims[f];
        #pragma unroll
        for (int j = 0; j < DMAXD; ++j) {
            w0[j] = __ldg(W + f * (DMAXD * EMB) + j * EMB + e);
            w1[j] = __ldg(W + f * (DMAXD * EMB) + j * EMB + e + 1);
        }
        b0 = __ldg(b + f * EMB + e);
        b1 = __ldg(b + f * EMB + e + 1);
    }

    const int rBase = blockIdx.x * RPB;

    if (rBase + RPB <= rows) {
        // ---- Fast path: 4 full tiles through the 3-slot DMA ring ----
        uint32_t mbs[PIPE], xss[PIPE];
        #pragma unroll
        for (int s = 0; s < PIPE; ++s) {
            mbs[s] = smem_u32(&mb[s]);
            xss[s] = smem_u32(xs[s]);
        }

        if (tid == 0) {
            #pragma unroll
            for (int s = 0; s < PIPE; ++s) mbar_init(mbs[s], 1);
            asm volatile("fence.proxy.async.shared::cta;" ::: "memory");
        }
        __syncthreads();

        // Prefetch tiles 0 and 1 (two-deep head start).
        if (tid == 0) {
            #pragma unroll
            for (int k = 0; k < PIPE - 1; ++k) {
                mbar_expect_tx(mbs[k], TILE_BYTES);
                bulk_g2s(xss[k], x + (size_t)(rBase + k * TR) * TOTALD,
                         TILE_BYTES, mbs[k]);
            }
        }

        #pragma unroll
        for (int t = 0; t < NTILES; ++t) {
            const int slot = t % PIPE;
            // Issue tile t+2 into slot (t+2)%PIPE. Its last reader (tile t-1)
            // finished before the end-of-iteration barrier of iter t-1, and
            // its mbarrier's last waiter also passed before that barrier.
            if (tid == 0 && t + (PIPE - 1) < NTILES) {
                const int ps = (t + PIPE - 1) % PIPE;
                mbar_expect_tx(mbs[ps], TILE_BYTES);
                bulk_g2s(xss[ps],
                         x + (size_t)(rBase + (t + PIPE - 1) * TR) * TOTALD,
                         TILE_BYTES, mbs[ps]);
            }
            // Wait for tile t; slot reused every PIPE tiles -> parity flips.
            mbar_wait(mbs[slot], (t / PIPE) & 1);

            if (active) {
                const int tileStart = rBase + t * TR;
                const float* xb = xs[slot];
                #pragma unroll 4
                for (int lr = rslot; lr < TR; lr += 2) {
                    const float* xr = xb + lr * TOTALD + off;
                    float s0 = b0, s1 = b1;
                    #pragma unroll
                    for (int j = 0; j < DMAXD; ++j) {
                        if (j < dim) {
                            const float xv = xr[j];
                            s0 = fmaf(xv, w0[j], s0);
                            s1 = fmaf(xv, w1[j], s1);
                        }
                    }
                    // warp writes 256B contiguous; .cs streams past L2
                    __stcs(reinterpret_cast<float2*>(
                               out + (size_t)(tileStart + lr) * CH + 2 * p),
                           make_float2(s0, s1));
                }
            }
            __syncthreads();   // last read of xs[slot]; refilled at iter t+1
        }
    } else {
        // ---- Tail path (unused for B=524288): synchronous staging ----
        for (int t0 = 0; t0 < RPB; t0 += TR) {
            const int tileStart = rBase + t0;
            if (tileStart >= rows) break;
            const int tileRows = min(TR, rows - tileStart);

            const float* src = x + (size_t)tileStart * TOTALD;
            for (int i = tid; i < tileRows * TOTALD; i += 256)
                xs[0][i] = __ldcs(src + i);
            __syncthreads();

            if (active) {
                for (int lr = rslot; lr < tileRows; lr += 2) {
                    const float* xr = xs[0] + lr * TOTALD + off;
                    float s0 = b0, s1 = b1;
                    #pragma unroll
                    for (int j = 0; j < DMAXD; ++j) {
                        if (j < dim) {
                            const float xv = xr[j];
                            s0 = fmaf(xv, w0[j], s0);
                            s1 = fmaf(xv, w1[j], s1);
                        }
                    }
                    __stcs(reinterpret_cast<float2*>(
                               out + (size_t)(tileStart + lr) * CH + 2 * p),
                           make_float2(s0, s1));
                }
            }
            __syncthreads();
        }
    }
}

extern "C" void kernel_launch(void* const* d_in, const int* in_sizes, int n_in,
                              void* d_out, int out_size)
{
    const float* x = (const float*)d_in[0];   // [B, 65] f32
    const float* W = (const float*)d_in[1];   // [23, 4, 10] f32 (masked)
    const float* b = (const float*)d_in[2];   // [23, 10] f32
    // d_in[3] = idx (int32) — compile-time constant metadata, ignored.
    float* out = (float*)d_out;               // [B, 23, 10] f32

    const int rows = in_sizes[0] / TOTALD;    // 524288
    const int grid = (rows + RPB - 1) / RPB;  // 4096

    Projection_5171140624940_kernel<<<grid, 256>>>(x, W, b, out, rows);
}